// round 10
// baseline (speedup 1.0000x reference)
#include <cuda_runtime.h>
#include <math.h>

#define R_TOT 2048   // B*C rows
#define N0 8192
#define M1 4099
#define M2 2053
#define M3 1030
#define M4 518
#define M1P 4100
#define M2P 2056
#define M3P 1032
#define M4P 520
#define CB 64
#define BB 32

__constant__ float c_dlo[8] = {-0.010597401784997278f, 0.032883011666982945f, 0.030841381835986965f,
                               -0.18703481171888114f, -0.02798376941698385f, 0.6308807679295904f,
                               0.7148465705525415f, 0.23037781330885523f};
__constant__ float c_dhi[8] = {-0.23037781330885523f, 0.7148465705525415f, -0.6308807679295904f,
                               -0.02798376941698385f, 0.18703481171888114f, 0.030841381835986965f,
                               -0.032883011666982945f, -0.010597401784997278f};

// Scratch (static device globals; allocation-free per harness rules)
__device__ __align__(256) float g_d1[(size_t)R_TOT * M1P];
__device__ __align__(256) float g_a2[(size_t)R_TOT * M2P];   // fwd a2, later reused for a2-recon
__device__ __align__(256) float g_d2[(size_t)R_TOT * M2P];
__device__ __align__(256) float g_d3[(size_t)R_TOT * M3P];
__device__ __align__(256) float g_a4[(size_t)R_TOT * M4P];
__device__ __align__(256) float g_d4[(size_t)R_TOT * M4P];
__device__ __align__(256) float g_a4t[(size_t)M4 * R_TOT];   // [k][row]
__device__ __align__(256) float g_d4t[(size_t)M4 * R_TOT];
__device__ __align__(256) float g_a4mt[(size_t)M4 * R_TOT];  // mix out, [k][row]
__device__ __align__(256) float g_d4mt[(size_t)M4 * R_TOT];
__device__ __align__(256) float g_a4m[(size_t)R_TOT * M4P];  // [row][k]
__device__ __align__(256) float g_d4m[(size_t)R_TOT * M4P];
__device__ __align__(256) float g_wt1[(size_t)M4 * CB * CB]; // [k][i*64+o]
__device__ __align__(256) float g_wt2[(size_t)M4 * CB * CB];

// ---------------------------------------------------------------------------
// K1: fused transpose + DWT L1 + DWT L2 with halo recompute.
// Block = (k2-tile of 64) x (b, c-half of 32). a1 lives only in SMEM.
// Even/odd split SMEM -> all tap reads stride-1 (conflict-free).
// ---------------------------------------------------------------------------
__global__ __launch_bounds__(256) void dwt12_kernel(const float* __restrict__ x,
                                                    float* __restrict__ d1,
                                                    float* __restrict__ a2,
                                                    float* __restrict__ d2) {
    extern __shared__ float sm[];
    float* xe = sm;                 // [32][139]
    float* xo = sm + 32 * 139;      // [32][139]
    float* ae = sm + 2 * 32 * 139;  // [32][68]  a1 even (global k1=2t)
    float* ao = ae + 32 * 68;       // [32][68]  a1 odd  (global k1=2t+1)
    int K0 = blockIdx.x * 64;
    int ct = blockIdx.y;
    int b = ct >> 1, c0 = (ct & 1) * 32;
    int tid = threadIdx.x;
    int xbase = 4 * K0 - 18;        // even

    // load x window (reflect at load): xe[u]=x_sym[xbase+2u], xo[u]=x_sym[xbase+2u+1]
    for (int idx = tid; idx < 276 * 32; idx += 256) {
        int nn = idx >> 5, cc = idx & 31;
        int q = xbase + nn;
        q = (q < 0) ? (-1 - q) : q;
        q = (q >= N0) ? (2 * N0 - 1 - q) : q;
        float v = __ldg(&x[((size_t)b * N0 + q) * CB + c0 + cc]);
        if (nn & 1) xo[cc * 139 + (nn >> 1)] = v;
        else        xe[cc * 139 + (nn >> 1)] = v;
    }
    __syncthreads();

    // a1 window [2K0-6, 2K0+127] (local kk 0..133); d1 owned for kk>=6
    for (int idx = tid; idx < 32 * 134; idx += 256) {
        int cc = idx / 134, kk = idx - cc * 134;
        int k1 = 2 * K0 - 6 + kk;
        if (k1 < 0 || k1 >= M1) continue;
        const float* pe = &xe[cc * 139 + kk + 3];  // u = kk+3-s
        const float* po = &xo[cc * 139 + kk + 3];
        float sa = 0.f, sd = 0.f;
#pragma unroll
        for (int s = 0; s < 4; s++) {
            float vo = po[-s], ve = pe[-s];
            sa = fmaf(vo, c_dlo[2 * s], fmaf(ve, c_dlo[2 * s + 1], sa));
            sd = fmaf(vo, c_dhi[2 * s], fmaf(ve, c_dhi[2 * s + 1], sd));
        }
        int tl = (k1 >> 1) - (K0 - 3);
        if (k1 & 1) ao[cc * 68 + tl] = sa;
        else        ae[cc * 68 + tl] = sa;
        if (kk >= 6) d1[(size_t)(b * 64 + c0 + cc) * M1P + k1] = sd;
    }
    __syncthreads();

    // level 2: a2/d2 for k2 in [K0, K0+63]
    for (int idx = tid; idx < 32 * 64; idx += 256) {
        int cc = idx >> 6, kk2 = idx & 63;
        int k2 = K0 + kk2;
        if (k2 >= M2) continue;
        float sa = 0.f, sd = 0.f;
        if (k2 >= 3 && k2 <= 2048) {  // interior: a1 taps 2k2-6..2k2+1 all valid
            const float* pe = &ae[cc * 68 + kk2 + 3];
            const float* po = &ao[cc * 68 + kk2 + 3];
#pragma unroll
            for (int s = 0; s < 4; s++) {
                float vo = po[-s], ve = pe[-s];
                sa = fmaf(vo, c_dlo[2 * s], fmaf(ve, c_dlo[2 * s + 1], sa));
                sd = fmaf(vo, c_dhi[2 * s], fmaf(ve, c_dhi[2 * s + 1], sd));
            }
        } else {
#pragma unroll
            for (int j = 0; j < 8; j++) {
                int g = 2 * k2 + 1 - j;
                g = (g < 0) ? (-1 - g) : g;
                g = (g >= M1) ? (2 * M1 - 1 - g) : g;
                int tl = (g >> 1) - (K0 - 3);
                float v = (g & 1) ? ao[cc * 68 + tl] : ae[cc * 68 + tl];
                sa = fmaf(v, c_dlo[j], sa);
                sd = fmaf(v, c_dhi[j], sd);
            }
        }
        size_t off = (size_t)(b * 64 + c0 + cc) * M2P + k2;
        a2[off] = sa;
        d2[off] = sd;
    }
}

// ---------------------------------------------------------------------------
// K2: fused DWT L3 + L4 per row. a3 lives only in SMEM.
// ---------------------------------------------------------------------------
__global__ __launch_bounds__(256) void dwt34_kernel(const float* __restrict__ a2,
                                                    float* __restrict__ d3,
                                                    float* __restrict__ a4,
                                                    float* __restrict__ d4) {
    __shared__ __align__(16) float s2e[1032];
    __shared__ __align__(16) float s2o[1032];
    __shared__ __align__(16) float a3e[520];
    __shared__ __align__(16) float a3o[520];
    int row = blockIdx.x, tid = threadIdx.x;
    const float4* s4 = reinterpret_cast<const float4*>(a2 + (size_t)row * M2P);
    for (int i = tid; i < 514; i += 256) {
        float4 v = __ldg(&s4[i]);
        int u = 2 * i;
        s2e[u] = v.x; s2o[u] = v.y; s2e[u + 1] = v.z; s2o[u + 1] = v.w;
    }
    __syncthreads();
    float* d3r = d3 + (size_t)row * M3P;
    for (int k = tid; k < M3; k += 256) {
        float sa = 0.f, sd = 0.f;
        if (k >= 3 && k <= 1025) {
#pragma unroll
            for (int s = 0; s < 4; s++) {
                float vo = s2o[k - s], ve = s2e[k - s];
                sa = fmaf(vo, c_dlo[2 * s], fmaf(ve, c_dlo[2 * s + 1], sa));
                sd = fmaf(vo, c_dhi[2 * s], fmaf(ve, c_dhi[2 * s + 1], sd));
            }
        } else {
#pragma unroll
            for (int j = 0; j < 8; j++) {
                int g = 2 * k + 1 - j;
                g = (g < 0) ? (-1 - g) : g;
                g = (g >= M2) ? (2 * M2 - 1 - g) : g;
                float v = (g & 1) ? s2o[g >> 1] : s2e[g >> 1];
                sa = fmaf(v, c_dlo[j], sa);
                sd = fmaf(v, c_dhi[j], sd);
            }
        }
        if (k & 1) a3o[k >> 1] = sa; else a3e[k >> 1] = sa;
        d3r[k] = sd;
    }
    __syncthreads();
    float* a4r = a4 + (size_t)row * M4P;
    float* d4r = d4 + (size_t)row * M4P;
    for (int k = tid; k < M4; k += 256) {
        float sa = 0.f, sd = 0.f;
        if (k >= 3 && k <= 514) {
#pragma unroll
            for (int s = 0; s < 4; s++) {
                float vo = a3o[k - s], ve = a3e[k - s];
                sa = fmaf(vo, c_dlo[2 * s], fmaf(ve, c_dlo[2 * s + 1], sa));
                sd = fmaf(vo, c_dhi[2 * s], fmaf(ve, c_dhi[2 * s + 1], sd));
            }
        } else {
#pragma unroll
            for (int j = 0; j < 8; j++) {
                int g = 2 * k + 1 - j;
                g = (g < 0) ? (-1 - g) : g;
                g = (g >= M3) ? (2 * M3 - 1 - g) : g;
                float v = (g & 1) ? a3o[g >> 1] : a3e[g >> 1];
                sa = fmaf(v, c_dlo[j], sa);
                sd = fmaf(v, c_dhi[j], sd);
            }
        }
        a4r[k] = sa;
        d4r[k] = sd;
    }
}

// ---------------------------------------------------------------------------
// Combined forward transposes (z=0: a4->a4t, 1: d4->d4t, 2: w1->wt1, 3: w2->wt2)
// ---------------------------------------------------------------------------
__global__ void tr4_kernel(const float* __restrict__ s0, const float* __restrict__ s1,
                           const float* __restrict__ s2, const float* __restrict__ s3,
                           float* __restrict__ o0, float* __restrict__ o1,
                           float* __restrict__ o2, float* __restrict__ o3) {
    __shared__ float tile[32][33];
    int z = blockIdx.z;
    const float* __restrict__ src; float* __restrict__ dst; int R, ss, ds;
    if (z == 0)      { src = s0; dst = o0; R = R_TOT; ss = M4P; ds = R_TOT; }
    else if (z == 1) { src = s1; dst = o1; R = R_TOT; ss = M4P; ds = R_TOT; }
    else if (z == 2) { src = s2; dst = o2; R = 4096;  ss = M4;  ds = 4096; }
    else             { src = s3; dst = o3; R = 4096;  ss = M4;  ds = 4096; }
    int c0 = blockIdx.x * 32;
    int r0 = blockIdx.y * 32;
    if (r0 >= R) return;
    int tx = threadIdx.x, ty = threadIdx.y;
#pragma unroll
    for (int i = 0; i < 32; i += 8) {
        int r = r0 + ty + i, c = c0 + tx;
        if (r < R && c < M4) tile[ty + i][tx] = src[(size_t)r * ss + c];
    }
    __syncthreads();
#pragma unroll
    for (int i = 0; i < 32; i += 8) {
        int c = c0 + ty + i, r = r0 + tx;
        if (c < M4 && r < R) dst[(size_t)c * ds + r] = tile[tx][ty + i];
    }
}

// ---------------------------------------------------------------------------
// Back transposes (z=0: a4mt->a4m, 1: d4mt->d4m)
// ---------------------------------------------------------------------------
__global__ void tr2_kernel(const float* __restrict__ s0, const float* __restrict__ s1,
                           float* __restrict__ o0, float* __restrict__ o1) {
    __shared__ float tile[32][33];
    const float* __restrict__ src = blockIdx.z ? s1 : s0;
    float* __restrict__ dst = blockIdx.z ? o1 : o0;
    int c0 = blockIdx.x * 32;
    int r0 = blockIdx.y * 32;
    int tx = threadIdx.x, ty = threadIdx.y;
#pragma unroll
    for (int i = 0; i < 32; i += 8) {
        int r = r0 + ty + i;
        if (r < M4) tile[ty + i][tx] = src[(size_t)r * R_TOT + c0 + tx];
    }
    __syncthreads();
#pragma unroll
    for (int i = 0; i < 32; i += 8) {
        int r = r0 + tx;
        if (r < M4) dst[(size_t)(c0 + ty + i) * M4P + r] = tile[tx][ty + i];
    }
}

// ---------------------------------------------------------------------------
// Channel mix (unchanged, proven)
// ---------------------------------------------------------------------------
__global__ __launch_bounds__(256) void mix_kernel(
    const float* __restrict__ a4t, const float* __restrict__ d4t,
    const float* __restrict__ wt1, const float* __restrict__ wt2,
    float* __restrict__ a4mt, float* __restrict__ d4mt) {
    int k = blockIdx.x;
    const float* __restrict__ in = blockIdx.y ? d4t : a4t;
    const float* __restrict__ wt = blockIdx.y ? wt2 : wt1;
    float* __restrict__ out = blockIdx.y ? d4mt : a4mt;

    __shared__ __align__(16) float ws[4096];
    __shared__ float as[32 * 65];
    int tid = threadIdx.x;
    const float4* __restrict__ wk4 = reinterpret_cast<const float4*>(wt + (size_t)k * 4096);
    const float4* __restrict__ ik4 = reinterpret_cast<const float4*>(in + (size_t)k * R_TOT);
    float4* ws4w = reinterpret_cast<float4*>(ws);
    for (int idx = tid; idx < 1024; idx += 256) ws4w[idx] = __ldg(&wk4[idx]);
    for (int idx = tid; idx < 512; idx += 256) {
        float4 v = __ldg(&ik4[idx]);
        int b = idx >> 4, i = (idx & 15) * 4;
        float* p = &as[b * 65 + i];
        p[0] = v.x; p[1] = v.y; p[2] = v.z; p[3] = v.w;
    }
    __syncthreads();

    int b = tid >> 3;
    int lg = tid & 7;
    const float4* ws4 = reinterpret_cast<const float4*>(ws);
    float4 acc0 = make_float4(0.f, 0.f, 0.f, 0.f);
    float4 acc1 = make_float4(0.f, 0.f, 0.f, 0.f);
#pragma unroll
    for (int i = 0; i < 64; i++) {
        float av = as[b * 65 + i];
        float4 w0 = ws4[i * 16 + lg];
        float4 w1 = ws4[i * 16 + 8 + lg];
        acc0.x = fmaf(av, w0.x, acc0.x); acc0.y = fmaf(av, w0.y, acc0.y);
        acc0.z = fmaf(av, w0.z, acc0.z); acc0.w = fmaf(av, w0.w, acc0.w);
        acc1.x = fmaf(av, w1.x, acc1.x); acc1.y = fmaf(av, w1.y, acc1.y);
        acc1.z = fmaf(av, w1.z, acc1.z); acc1.w = fmaf(av, w1.w, acc1.w);
    }
    float4* ok = reinterpret_cast<float4*>(out + (size_t)k * R_TOT + b * 64);
    ok[lg] = acc0;
    ok[8 + lg] = acc1;
}

// ---------------------------------------------------------------------------
// K6: fused IDWT L4->3 + L3->2 per row. a3 only in SMEM. Writes a2-recon.
// All SMEM arrays 16B-aligned, sizes multiples of 4 (float4 access safe).
// ---------------------------------------------------------------------------
__global__ __launch_bounds__(256) void idwt432_kernel(const float* __restrict__ a4m,
                                                      const float* __restrict__ d4m,
                                                      const float* __restrict__ d3,
                                                      float* __restrict__ a2r) {
    __shared__ __align__(16) float sa4[520];
    __shared__ __align__(16) float sd4[520];
    __shared__ __align__(16) float sa3[1032];
    __shared__ __align__(16) float sd3[1032];
    int row = blockIdx.x, tid = threadIdx.x;
    const float4* pa = reinterpret_cast<const float4*>(a4m + (size_t)row * M4P);
    const float4* pd = reinterpret_cast<const float4*>(d4m + (size_t)row * M4P);
    for (int i = tid; i < 130; i += 256) {
        *reinterpret_cast<float4*>(&sa4[4 * i]) = __ldg(&pa[i]);
        *reinterpret_cast<float4*>(&sd4[4 * i]) = __ldg(&pd[i]);
    }
    const float4* p3 = reinterpret_cast<const float4*>(d3 + (size_t)row * M3P);
    for (int i = tid; i < 258; i += 256)
        *reinterpret_cast<float4*>(&sd3[4 * i]) = __ldg(&p3[i]);
    __syncthreads();

    for (int p = tid; p < M3; p += 256) {
        int q = p >> 1;
        float s = 0.f;
        if (p & 1) {
#pragma unroll
            for (int t = 0; t < 4; t++)
                s = fmaf(sa4[q + t], c_dlo[2 * t], fmaf(sd4[q + t], c_dhi[2 * t], s));
        } else {
#pragma unroll
            for (int t = 0; t < 4; t++)
                s = fmaf(sa4[q + t], c_dlo[2 * t + 1], fmaf(sd4[q + t], c_dhi[2 * t + 1], s));
        }
        sa3[p] = s;
    }
    __syncthreads();

    float* outr = a2r + (size_t)row * M2P;
    for (int p = tid; p < M2; p += 256) {
        int q = p >> 1;
        float s = 0.f;
        if (p & 1) {
#pragma unroll
            for (int t = 0; t < 4; t++)
                s = fmaf(sa3[q + t], c_dlo[2 * t], fmaf(sd3[q + t], c_dhi[2 * t], s));
        } else {
#pragma unroll
            for (int t = 0; t < 4; t++)
                s = fmaf(sa3[q + t], c_dlo[2 * t + 1], fmaf(sd3[q + t], c_dhi[2 * t + 1], s));
        }
        outr[p] = s;
    }
}

// ---------------------------------------------------------------------------
// K7: fused IDWT L2->1 + L1->0 + transpose-back + dense shortcut + mish.
// ---------------------------------------------------------------------------
__device__ __forceinline__ float mish_f(float v) {
    float sp = (v > 20.f) ? v : log1pf(expf(v));
    return v * tanhf(sp);
}

__global__ __launch_bounds__(256) void ifinal2_kernel(
    const float* __restrict__ a2r, const float* __restrict__ d2,
    const float* __restrict__ d1, const float* __restrict__ x,
    const float* __restrict__ dk, const float* __restrict__ bias,
    float* __restrict__ out) {
    extern __shared__ float sm[];
    float* dks = sm;            // 4096  (16B aligned: offset 0)
    float* xs  = sm + 4096;     // 32*65 = 2080
    float* ys  = xs + 2080;     // 2080
    float* sA  = ys + 2080;     // 64*20 = 1280  (a1 recon window)
    float* sD  = sA + 1280;     // 1280          (d1 window)
    float* sA2 = sD + 1280;     // 64*14 = 896
    float* sD2 = sA2 + 896;     // 896
    float* bs  = sD2 + 896;     // 64

    int b = blockIdx.y;
    int n0 = blockIdx.x * 32;
    int r0 = n0 >> 1;   // even
    int q0 = r0 >> 1;
    int tid = threadIdx.x;

    for (int idx = tid; idx < 4096; idx += 256) dks[idx] = __ldg(&dk[idx]);
    if (tid < 64) bs[tid] = __ldg(&bias[tid]);
    for (int idx = tid; idx < 64 * 13; idx += 256) {
        int c = idx / 13, i = idx - c * 13;
        size_t off = (size_t)(b * 64 + c) * M2P + q0 + i;
        sA2[c * 14 + i] = __ldg(&a2r[off]);
        sD2[c * 14 + i] = __ldg(&d2[off]);
    }
    for (int idx = tid; idx < 64 * 19; idx += 256) {
        int c = idx / 19, i = idx - c * 19;
        sD[c * 20 + i] = __ldg(&d1[(size_t)(b * 64 + c) * M1P + r0 + i]);
    }
    for (int idx = tid; idx < 2048; idx += 256) {
        int nn = idx >> 6, i = idx & 63;
        xs[nn * 65 + i] = __ldg(&x[((size_t)b * N0 + n0 + nn) * CB + i]);
    }
    __syncthreads();

    // reconstruct a1 window: sA[c][rr], rr 0..18, r = r0+rr (parity(r)=parity(rr))
    for (int idx = tid; idx < 64 * 19; idx += 256) {
        int c = idx / 19, rr = idx - c * 19;
        int ql = rr >> 1;
        const float* A = &sA2[c * 14 + ql];
        const float* D = &sD2[c * 14 + ql];
        float s = 0.f;
        if (rr & 1) {
#pragma unroll
            for (int t = 0; t < 4; t++)
                s = fmaf(A[t], c_dlo[2 * t], fmaf(D[t], c_dhi[2 * t], s));
        } else {
#pragma unroll
            for (int t = 0; t < 4; t++)
                s = fmaf(A[t], c_dlo[2 * t + 1], fmaf(D[t], c_dhi[2 * t + 1], s));
        }
        sA[c * 20 + rr] = s;
    }
    __syncthreads();

    // IDWT level 1 into ys[nn][c]
#pragma unroll
    for (int s = 0; s < 8; s++) {
        int oi = s * 256 + tid;
        int c = oi >> 5, nn = oi & 31;
        int ri = nn >> 1;
        const float* A = &sA[c * 20 + ri];
        const float* D = &sD[c * 20 + ri];
        float sv = 0.f;
        if (nn & 1) {
#pragma unroll
            for (int t = 0; t < 4; t++)
                sv = fmaf(A[t], c_dlo[2 * t], fmaf(D[t], c_dhi[2 * t], sv));
        } else {
#pragma unroll
            for (int t = 0; t < 4; t++)
                sv = fmaf(A[t], c_dlo[2 * t + 1], fmaf(D[t], c_dhi[2 * t + 1], sv));
        }
        ys[nn * 65 + c] = sv;
    }
    __syncthreads();

    // dense shortcut + add + mish
    int nn = tid >> 3;
    int lg = tid & 7;
    int g = lg * 4;
    const float4* dk4 = reinterpret_cast<const float4*>(dks);
    float4 acc0 = make_float4(bs[g], bs[g + 1], bs[g + 2], bs[g + 3]);
    float4 acc1 = make_float4(bs[g + 32], bs[g + 33], bs[g + 34], bs[g + 35]);
#pragma unroll
    for (int i = 0; i < 64; i++) {
        float xv = xs[nn * 65 + i];
        float4 w0 = dk4[i * 16 + lg];
        float4 w1 = dk4[i * 16 + 8 + lg];
        acc0.x = fmaf(xv, w0.x, acc0.x); acc0.y = fmaf(xv, w0.y, acc0.y);
        acc0.z = fmaf(xv, w0.z, acc0.z); acc0.w = fmaf(xv, w0.w, acc0.w);
        acc1.x = fmaf(xv, w1.x, acc1.x); acc1.y = fmaf(xv, w1.y, acc1.y);
        acc1.z = fmaf(xv, w1.z, acc1.z); acc1.w = fmaf(xv, w1.w, acc1.w);
    }
    float v0[4] = {acc0.x, acc0.y, acc0.z, acc0.w};
    float v1[4] = {acc1.x, acc1.y, acc1.z, acc1.w};
#pragma unroll
    for (int u = 0; u < 4; u++) {
        v0[u] = mish_f(v0[u] + ys[nn * 65 + g + u]);
        v1[u] = mish_f(v1[u] + ys[nn * 65 + g + 32 + u]);
    }
    float4* op = reinterpret_cast<float4*>(&out[((size_t)b * N0 + n0 + nn) * CB]);
    op[lg] = make_float4(v0[0], v0[1], v0[2], v0[3]);
    op[8 + lg] = make_float4(v1[0], v1[1], v1[2], v1[3]);
}

// ---------------------------------------------------------------------------
extern "C" void kernel_launch(void* const* d_in, const int* in_sizes, int n_in,
                              void* d_out, int out_size) {
    (void)in_sizes; (void)n_in; (void)out_size;
    const float* x    = (const float*)d_in[0];
    const float* w1   = (const float*)d_in[1];
    const float* w2   = (const float*)d_in[2];
    const float* dk   = (const float*)d_in[3];
    const float* bias = (const float*)d_in[4];
    float* out = (float*)d_out;

    float *d1, *a2, *d2, *d3, *a4, *d4;
    float *a4t, *d4t, *a4mt, *d4mt, *a4m, *d4m, *wt1, *wt2;
    cudaGetSymbolAddress((void**)&d1,   g_d1);
    cudaGetSymbolAddress((void**)&a2,   g_a2);
    cudaGetSymbolAddress((void**)&d2,   g_d2);
    cudaGetSymbolAddress((void**)&d3,   g_d3);
    cudaGetSymbolAddress((void**)&a4,   g_a4);
    cudaGetSymbolAddress((void**)&d4,   g_d4);
    cudaGetSymbolAddress((void**)&a4t,  g_a4t);
    cudaGetSymbolAddress((void**)&d4t,  g_d4t);
    cudaGetSymbolAddress((void**)&a4mt, g_a4mt);
    cudaGetSymbolAddress((void**)&d4mt, g_d4mt);
    cudaGetSymbolAddress((void**)&a4m,  g_a4m);
    cudaGetSymbolAddress((void**)&d4m,  g_d4m);
    cudaGetSymbolAddress((void**)&wt1,  g_wt1);
    cudaGetSymbolAddress((void**)&wt2,  g_wt2);

    const int K1_SMEM = (2 * 32 * 139 + 2 * 32 * 68) * (int)sizeof(float);  // 52992 B
    const int K7_SMEM = (4096 + 2080 + 2080 + 1280 + 1280 + 896 + 896 + 64) * (int)sizeof(float); // 50688 B
    cudaFuncSetAttribute(dwt12_kernel, cudaFuncAttributeMaxDynamicSharedMemorySize, K1_SMEM);
    cudaFuncSetAttribute(ifinal2_kernel, cudaFuncAttributeMaxDynamicSharedMemorySize, K7_SMEM);

    dim3 trb(32, 8);
    // 1. fused transpose + DWT L1 + L2 (a1 never hits gmem)
    dwt12_kernel<<<dim3(33, 64), 256, K1_SMEM>>>(x, d1, a2, d2);
    // 2. fused DWT L3 + L4 per row (a3 in SMEM)
    dwt34_kernel<<<R_TOT, 256>>>(a2, d3, a4, d4);
    // 3. forward transposes (a4,d4,w1,w2 -> k-major)
    tr4_kernel<<<dim3((M4 + 31) / 32, 4096 / 32, 4), trb>>>(a4, d4, w1, w2, a4t, d4t, wt1, wt2);
    // 4. channel mix
    mix_kernel<<<dim3(M4, 2), 256>>>(a4t, d4t, wt1, wt2, a4mt, d4mt);
    // 5. transpose mixed back to row-major
    tr2_kernel<<<dim3(R_TOT / 32, (M4 + 31) / 32, 2), trb>>>(a4mt, d4mt, a4m, d4m);
    // 6. fused IDWT L4->3->2 per row (a3 in SMEM); overwrites dead fwd a2
    idwt432_kernel<<<R_TOT, 256>>>(a4m, d4m, d3, a2);
    // 7. fused IDWT L2->1 + L1->0 + transpose-back + dense + mish
    ifinal2_kernel<<<dim3(N0 / 32, BB), 256, K7_SMEM>>>(a2, d2, d1, x, dk, bias, out);
}

// round 11
// speedup vs baseline: 1.1468x; 1.1468x over previous
#include <cuda_runtime.h>
#include <math.h>

#define R_TOT 2048   // B*C rows
#define N0 8192
#define M1 4099
#define M2 2053
#define M3 1030
#define M4 518
#define M1P 4100
#define M2P 2056
#define M3P 1032
#define M4P 520
#define CB 64
#define BB 32

__constant__ float c_dlo[8] = {-0.010597401784997278f, 0.032883011666982945f, 0.030841381835986965f,
                               -0.18703481171888114f, -0.02798376941698385f, 0.6308807679295904f,
                               0.7148465705525415f, 0.23037781330885523f};
__constant__ float c_dhi[8] = {-0.23037781330885523f, 0.7148465705525415f, -0.6308807679295904f,
                               -0.02798376941698385f, 0.18703481171888114f, 0.030841381835986965f,
                               -0.032883011666982945f, -0.010597401784997278f};
// packed (dlo[j], dhi[j]) pairs for f32x2 math
__constant__ float2 c_lh[8] = {
    {-0.010597401784997278f, -0.23037781330885523f},
    {0.032883011666982945f,  0.7148465705525415f},
    {0.030841381835986965f,  -0.6308807679295904f},
    {-0.18703481171888114f,  -0.02798376941698385f},
    {-0.02798376941698385f,  0.18703481171888114f},
    {0.6308807679295904f,    0.030841381835986965f},
    {0.7148465705525415f,    -0.032883011666982945f},
    {0.23037781330885523f,   -0.010597401784997278f}};

typedef unsigned long long u64;
__device__ __forceinline__ u64 ffma2(u64 a, u64 b, u64 c) {
    u64 d;
    asm("fma.rn.f32x2 %0, %1, %2, %3;" : "=l"(d) : "l"(a), "l"(b), "l"(c));
    return d;
}
__device__ __forceinline__ u64 pk2(float x, float y) {
    u64 r;
    asm("mov.b64 %0, {%1, %2};" : "=l"(r) : "f"(x), "f"(y));
    return r;
}
__device__ __forceinline__ float2 up2(u64 v) {
    float2 r;
    asm("mov.b64 {%0, %1}, %2;" : "=f"(r.x), "=f"(r.y) : "l"(v));
    return r;
}

// Scratch (static device globals; allocation-free per harness rules)
__device__ __align__(256) float g_d1[(size_t)R_TOT * M1P];
__device__ __align__(256) float g_a2[(size_t)R_TOT * M2P];   // fwd a2, later a2-recon
__device__ __align__(256) float g_d2[(size_t)R_TOT * M2P];
__device__ __align__(256) float g_d3[(size_t)R_TOT * M3P];
__device__ __align__(256) float g_a4[(size_t)R_TOT * M4P];
__device__ __align__(256) float g_d4[(size_t)R_TOT * M4P];
__device__ __align__(256) float g_a4t[(size_t)M4 * R_TOT];   // [k][row]
__device__ __align__(256) float g_d4t[(size_t)M4 * R_TOT];
__device__ __align__(256) float g_a4mt[(size_t)M4 * R_TOT];
__device__ __align__(256) float g_d4mt[(size_t)M4 * R_TOT];
__device__ __align__(256) float g_a4m[(size_t)R_TOT * M4P];  // [row][k]
__device__ __align__(256) float g_d4m[(size_t)R_TOT * M4P];
__device__ __align__(256) float g_wt1[(size_t)M4 * CB * CB]; // [k][i*64+o]
__device__ __align__(256) float g_wt2[(size_t)M4 * CB * CB];

// ---------------------------------------------------------------------------
// K1: fused transpose + DWT L1 + L2 (halo recompute). a1 only in SMEM.
// ---------------------------------------------------------------------------
__global__ __launch_bounds__(256) void dwt12_kernel(const float* __restrict__ x,
                                                    float* __restrict__ d1,
                                                    float* __restrict__ a2,
                                                    float* __restrict__ d2) {
    extern __shared__ float sm[];
    float* xe = sm;                 // [32][139]
    float* xo = sm + 32 * 139;      // [32][139]
    float* ae = sm + 2 * 32 * 139;  // [32][68]
    float* ao = ae + 32 * 68;       // [32][68]
    int K0 = blockIdx.x * 64;
    int ct = blockIdx.y;
    int b = ct >> 1, c0 = (ct & 1) * 32;
    int tid = threadIdx.x;
    int xbase = 4 * K0 - 18;        // even
    const u64* lh = reinterpret_cast<const u64*>(c_lh);

    // x window via float4 over channels: 276 rows x 8 cgroups
    for (int idx = tid; idx < 276 * 8; idx += 256) {
        int nn = idx >> 3, cg = idx & 7;
        int q = xbase + nn;
        q = (q < 0) ? (-1 - q) : q;
        q = (q >= N0) ? (2 * N0 - 1 - q) : q;
        float4 v = __ldg(reinterpret_cast<const float4*>(&x[((size_t)b * N0 + q) * CB + c0 + cg * 4]));
        int u = nn >> 1;
        float* dst = (nn & 1) ? xo : xe;
        int cb4 = cg * 4;
        dst[(cb4 + 0) * 139 + u] = v.x;
        dst[(cb4 + 1) * 139 + u] = v.y;
        dst[(cb4 + 2) * 139 + u] = v.z;
        dst[(cb4 + 3) * 139 + u] = v.w;
    }
    __syncthreads();

    // a1 window [2K0-6, 2K0+127]; d1 owned for kk>=6
    for (int idx = tid; idx < 32 * 134; idx += 256) {
        int cc = idx / 134, kk = idx - cc * 134;
        int k1 = 2 * K0 - 6 + kk;
        if (k1 < 0 || k1 >= M1) continue;
        const float* pe = &xe[cc * 139 + kk + 3];
        const float* po = &xo[cc * 139 + kk + 3];
        u64 acc = 0ull;
#pragma unroll
        for (int s = 0; s < 4; s++) {
            float vo = po[-s], ve = pe[-s];
            acc = ffma2(pk2(vo, vo), lh[2 * s], acc);
            acc = ffma2(pk2(ve, ve), lh[2 * s + 1], acc);
        }
        float2 ad = up2(acc);
        int tl = (k1 >> 1) - (K0 - 3);
        if (k1 & 1) ao[cc * 68 + tl] = ad.x;
        else        ae[cc * 68 + tl] = ad.x;
        if (kk >= 6) d1[(size_t)(b * 64 + c0 + cc) * M1P + k1] = ad.y;
    }
    __syncthreads();

    // level 2
    for (int idx = tid; idx < 32 * 64; idx += 256) {
        int cc = idx >> 6, kk2 = idx & 63;
        int k2 = K0 + kk2;
        if (k2 >= M2) continue;
        float sa, sd;
        if (k2 >= 3 && k2 <= 2048) {
            const float* pe = &ae[cc * 68 + kk2 + 3];
            const float* po = &ao[cc * 68 + kk2 + 3];
            u64 acc = 0ull;
#pragma unroll
            for (int s = 0; s < 4; s++) {
                float vo = po[-s], ve = pe[-s];
                acc = ffma2(pk2(vo, vo), lh[2 * s], acc);
                acc = ffma2(pk2(ve, ve), lh[2 * s + 1], acc);
            }
            float2 ad = up2(acc);
            sa = ad.x; sd = ad.y;
        } else {
            sa = 0.f; sd = 0.f;
#pragma unroll
            for (int j = 0; j < 8; j++) {
                int g = 2 * k2 + 1 - j;
                g = (g < 0) ? (-1 - g) : g;
                g = (g >= M1) ? (2 * M1 - 1 - g) : g;
                int tl = (g >> 1) - (K0 - 3);
                float v = (g & 1) ? ao[cc * 68 + tl] : ae[cc * 68 + tl];
                sa = fmaf(v, c_dlo[j], sa);
                sd = fmaf(v, c_dhi[j], sd);
            }
        }
        size_t off = (size_t)(b * 64 + c0 + cc) * M2P + k2;
        a2[off] = sa;
        d2[off] = sd;
    }
}

// ---------------------------------------------------------------------------
// K2: fused DWT L3 + L4 per row. a3 only in SMEM.
// ---------------------------------------------------------------------------
__global__ __launch_bounds__(256) void dwt34_kernel(const float* __restrict__ a2,
                                                    float* __restrict__ d3,
                                                    float* __restrict__ a4,
                                                    float* __restrict__ d4) {
    __shared__ __align__(16) float s2e[1032];
    __shared__ __align__(16) float s2o[1032];
    __shared__ __align__(16) float a3e[520];
    __shared__ __align__(16) float a3o[520];
    int row = blockIdx.x, tid = threadIdx.x;
    const u64* lh = reinterpret_cast<const u64*>(c_lh);
    const float4* s4 = reinterpret_cast<const float4*>(a2 + (size_t)row * M2P);
    for (int i = tid; i < 514; i += 256) {
        float4 v = __ldg(&s4[i]);
        int u = 2 * i;
        s2e[u] = v.x; s2o[u] = v.y; s2e[u + 1] = v.z; s2o[u + 1] = v.w;
    }
    __syncthreads();
    float* d3r = d3 + (size_t)row * M3P;
    for (int k = tid; k < M3; k += 256) {
        float sa, sd;
        if (k >= 3 && k <= 1025) {
            u64 acc = 0ull;
#pragma unroll
            for (int s = 0; s < 4; s++) {
                float vo = s2o[k - s], ve = s2e[k - s];
                acc = ffma2(pk2(vo, vo), lh[2 * s], acc);
                acc = ffma2(pk2(ve, ve), lh[2 * s + 1], acc);
            }
            float2 ad = up2(acc);
            sa = ad.x; sd = ad.y;
        } else {
            sa = 0.f; sd = 0.f;
#pragma unroll
            for (int j = 0; j < 8; j++) {
                int g = 2 * k + 1 - j;
                g = (g < 0) ? (-1 - g) : g;
                g = (g >= M2) ? (2 * M2 - 1 - g) : g;
                float v = (g & 1) ? s2o[g >> 1] : s2e[g >> 1];
                sa = fmaf(v, c_dlo[j], sa);
                sd = fmaf(v, c_dhi[j], sd);
            }
        }
        if (k & 1) a3o[k >> 1] = sa; else a3e[k >> 1] = sa;
        d3r[k] = sd;
    }
    __syncthreads();
    float* a4r = a4 + (size_t)row * M4P;
    float* d4r = d4 + (size_t)row * M4P;
    for (int k = tid; k < M4; k += 256) {
        float sa, sd;
        if (k >= 3 && k <= 514) {
            u64 acc = 0ull;
#pragma unroll
            for (int s = 0; s < 4; s++) {
                float vo = a3o[k - s], ve = a3e[k - s];
                acc = ffma2(pk2(vo, vo), lh[2 * s], acc);
                acc = ffma2(pk2(ve, ve), lh[2 * s + 1], acc);
            }
            float2 ad = up2(acc);
            sa = ad.x; sd = ad.y;
        } else {
            sa = 0.f; sd = 0.f;
#pragma unroll
            for (int j = 0; j < 8; j++) {
                int g = 2 * k + 1 - j;
                g = (g < 0) ? (-1 - g) : g;
                g = (g >= M3) ? (2 * M3 - 1 - g) : g;
                float v = (g & 1) ? a3o[g >> 1] : a3e[g >> 1];
                sa = fmaf(v, c_dlo[j], sa);
                sd = fmaf(v, c_dhi[j], sd);
            }
        }
        a4r[k] = sa;
        d4r[k] = sd;
    }
}

// ---------------------------------------------------------------------------
// Forward transposes (z=0: a4->a4t, 1: d4->d4t, 2: w1->wt1, 3: w2->wt2)
// ---------------------------------------------------------------------------
__global__ void tr4_kernel(const float* __restrict__ s0, const float* __restrict__ s1,
                           const float* __restrict__ s2, const float* __restrict__ s3,
                           float* __restrict__ o0, float* __restrict__ o1,
                           float* __restrict__ o2, float* __restrict__ o3) {
    __shared__ float tile[32][33];
    int z = blockIdx.z;
    const float* __restrict__ src; float* __restrict__ dst; int R, ss, ds;
    if (z == 0)      { src = s0; dst = o0; R = R_TOT; ss = M4P; ds = R_TOT; }
    else if (z == 1) { src = s1; dst = o1; R = R_TOT; ss = M4P; ds = R_TOT; }
    else if (z == 2) { src = s2; dst = o2; R = 4096;  ss = M4;  ds = 4096; }
    else             { src = s3; dst = o3; R = 4096;  ss = M4;  ds = 4096; }
    int c0 = blockIdx.x * 32;
    int r0 = blockIdx.y * 32;
    if (r0 >= R) return;
    int tx = threadIdx.x, ty = threadIdx.y;
#pragma unroll
    for (int i = 0; i < 32; i += 8) {
        int r = r0 + ty + i, c = c0 + tx;
        if (r < R && c < M4) tile[ty + i][tx] = src[(size_t)r * ss + c];
    }
    __syncthreads();
#pragma unroll
    for (int i = 0; i < 32; i += 8) {
        int c = c0 + ty + i, r = r0 + tx;
        if (c < M4 && r < R) dst[(size_t)c * ds + r] = tile[tx][ty + i];
    }
}

// ---------------------------------------------------------------------------
// Back transposes (z=0: a4mt->a4m, 1: d4mt->d4m)
// ---------------------------------------------------------------------------
__global__ void tr2_kernel(const float* __restrict__ s0, const float* __restrict__ s1,
                           float* __restrict__ o0, float* __restrict__ o1) {
    __shared__ float tile[32][33];
    const float* __restrict__ src = blockIdx.z ? s1 : s0;
    float* __restrict__ dst = blockIdx.z ? o1 : o0;
    int c0 = blockIdx.x * 32;
    int r0 = blockIdx.y * 32;
    int tx = threadIdx.x, ty = threadIdx.y;
#pragma unroll
    for (int i = 0; i < 32; i += 8) {
        int r = r0 + ty + i;
        if (r < M4) tile[ty + i][tx] = src[(size_t)r * R_TOT + c0 + tx];
    }
    __syncthreads();
#pragma unroll
    for (int i = 0; i < 32; i += 8) {
        int r = r0 + tx;
        if (r < M4) dst[(size_t)(c0 + ty + i) * M4P + r] = tile[tx][ty + i];
    }
}

// ---------------------------------------------------------------------------
// Channel mix (proven, unchanged)
// ---------------------------------------------------------------------------
__global__ __launch_bounds__(256) void mix_kernel(
    const float* __restrict__ a4t, const float* __restrict__ d4t,
    const float* __restrict__ wt1, const float* __restrict__ wt2,
    float* __restrict__ a4mt, float* __restrict__ d4mt) {
    int k = blockIdx.x;
    const float* __restrict__ in = blockIdx.y ? d4t : a4t;
    const float* __restrict__ wt = blockIdx.y ? wt2 : wt1;
    float* __restrict__ out = blockIdx.y ? d4mt : a4mt;

    __shared__ __align__(16) float ws[4096];
    __shared__ float as[32 * 65];
    int tid = threadIdx.x;
    const float4* __restrict__ wk4 = reinterpret_cast<const float4*>(wt + (size_t)k * 4096);
    const float4* __restrict__ ik4 = reinterpret_cast<const float4*>(in + (size_t)k * R_TOT);
    float4* ws4w = reinterpret_cast<float4*>(ws);
    for (int idx = tid; idx < 1024; idx += 256) ws4w[idx] = __ldg(&wk4[idx]);
    for (int idx = tid; idx < 512; idx += 256) {
        float4 v = __ldg(&ik4[idx]);
        int b = idx >> 4, i = (idx & 15) * 4;
        float* p = &as[b * 65 + i];
        p[0] = v.x; p[1] = v.y; p[2] = v.z; p[3] = v.w;
    }
    __syncthreads();

    int b = tid >> 3;
    int lg = tid & 7;
    const float4* ws4 = reinterpret_cast<const float4*>(ws);
    float4 acc0 = make_float4(0.f, 0.f, 0.f, 0.f);
    float4 acc1 = make_float4(0.f, 0.f, 0.f, 0.f);
#pragma unroll
    for (int i = 0; i < 64; i++) {
        float av = as[b * 65 + i];
        float4 w0 = ws4[i * 16 + lg];
        float4 w1 = ws4[i * 16 + 8 + lg];
        acc0.x = fmaf(av, w0.x, acc0.x); acc0.y = fmaf(av, w0.y, acc0.y);
        acc0.z = fmaf(av, w0.z, acc0.z); acc0.w = fmaf(av, w0.w, acc0.w);
        acc1.x = fmaf(av, w1.x, acc1.x); acc1.y = fmaf(av, w1.y, acc1.y);
        acc1.z = fmaf(av, w1.z, acc1.z); acc1.w = fmaf(av, w1.w, acc1.w);
    }
    float4* ok = reinterpret_cast<float4*>(out + (size_t)k * R_TOT + b * 64);
    ok[lg] = acc0;
    ok[8 + lg] = acc1;
}

// ---------------------------------------------------------------------------
// K6: fused IDWT L4->3 + L3->2 per row (pair outputs via f32x2).
// ---------------------------------------------------------------------------
__global__ __launch_bounds__(256) void idwt432_kernel(const float* __restrict__ a4m,
                                                      const float* __restrict__ d4m,
                                                      const float* __restrict__ d3,
                                                      float* __restrict__ a2r) {
    __shared__ __align__(16) float sa4[520];
    __shared__ __align__(16) float sd4[520];
    __shared__ __align__(16) float sa3[1032];
    __shared__ __align__(16) float sd3[1032];
    int row = blockIdx.x, tid = threadIdx.x;
    const u64* lh = reinterpret_cast<const u64*>(c_lh);
    const float4* pa = reinterpret_cast<const float4*>(a4m + (size_t)row * M4P);
    const float4* pd = reinterpret_cast<const float4*>(d4m + (size_t)row * M4P);
    for (int i = tid; i < 130; i += 256) {
        *reinterpret_cast<float4*>(&sa4[4 * i]) = __ldg(&pa[i]);
        *reinterpret_cast<float4*>(&sd4[4 * i]) = __ldg(&pd[i]);
    }
    const float4* p3 = reinterpret_cast<const float4*>(d3 + (size_t)row * M3P);
    for (int i = tid; i < 258; i += 256)
        *reinterpret_cast<float4*>(&sd3[4 * i]) = __ldg(&p3[i]);
    __syncthreads();

    for (int q = tid; q < (M3 + 1) / 2; q += 256) {
        u64 accE = 0ull, accO = 0ull;
#pragma unroll
        for (int t = 0; t < 4; t++) {
            u64 ad = pk2(sa4[q + t], sd4[q + t]);
            accE = ffma2(ad, lh[2 * t + 1], accE);
            accO = ffma2(ad, lh[2 * t], accO);
        }
        float2 e = up2(accE), o = up2(accO);
        sa3[2 * q] = e.x + e.y;
        if (2 * q + 1 < M3) sa3[2 * q + 1] = o.x + o.y;
    }
    __syncthreads();

    float* outr = a2r + (size_t)row * M2P;
    for (int q = tid; q < (M2 + 1) / 2; q += 256) {
        u64 accE = 0ull, accO = 0ull;
#pragma unroll
        for (int t = 0; t < 4; t++) {
            u64 ad = pk2(sa3[q + t], sd3[q + t]);
            accE = ffma2(ad, lh[2 * t + 1], accE);
            accO = ffma2(ad, lh[2 * t], accO);
        }
        float2 e = up2(accE), o = up2(accO);
        outr[2 * q] = e.x + e.y;
        if (2 * q + 1 < M2) outr[2 * q + 1] = o.x + o.y;
    }
}

// ---------------------------------------------------------------------------
// K7: fused IDWT L2->1 + L1->0 + transpose-back + dense (f32x2) + mish.
// Block = (n-tile 64, b), 256 threads, 4096 blocks.
// ---------------------------------------------------------------------------
__device__ __forceinline__ float mish_f(float v) {
    float sp = (v > 20.f) ? v : log1pf(expf(v));
    return v * tanhf(sp);
}

__global__ __launch_bounds__(256) void ifinal2_kernel(
    const float* __restrict__ a2r, const float* __restrict__ d2,
    const float* __restrict__ d1, const float* __restrict__ x,
    const float* __restrict__ dk, const float* __restrict__ bias,
    float* __restrict__ out) {
    extern __shared__ float sm[];
    float* dks = sm;            // 4096
    float* xs  = sm + 4096;     // 64*65 = 4160
    float* ys  = xs + 4160;     // 4160
    float* sA  = ys + 4160;     // 64*36 = 2304 (a1 recon window, 35 used)
    float* sD  = sA + 2304;     // 2304          (d1 window, 35 used)
    float* sA2 = sD + 2304;     // 64*22 = 1408 (21 used)
    float* sD2 = sA2 + 1408;    // 1408
    float* bs  = sD2 + 1408;    // 64

    int b = blockIdx.y;
    int n0 = blockIdx.x * 64;
    int r0 = n0 >> 1;   // even
    int q0 = r0 >> 1;
    int tid = threadIdx.x;
    const u64* lh = reinterpret_cast<const u64*>(c_lh);

    {   // dk via float4
        const float4* dk4g = reinterpret_cast<const float4*>(dk);
        float4* dks4 = reinterpret_cast<float4*>(dks);
        for (int idx = tid; idx < 1024; idx += 256) dks4[idx] = __ldg(&dk4g[idx]);
    }
    if (tid < 64) bs[tid] = __ldg(&bias[tid]);
    for (int idx = tid; idx < 64 * 21; idx += 256) {
        int c = idx / 21, i = idx - c * 21;
        size_t off = (size_t)(b * 64 + c) * M2P + q0 + i;
        sA2[c * 22 + i] = __ldg(&a2r[off]);
        sD2[c * 22 + i] = __ldg(&d2[off]);
    }
    for (int idx = tid; idx < 64 * 35; idx += 256) {
        int c = idx / 35, i = idx - c * 35;
        sD[c * 36 + i] = __ldg(&d1[(size_t)(b * 64 + c) * M1P + r0 + i]);
    }
    {   // x tile via float4: 64 nn x 16 groups
        const float4* xg = reinterpret_cast<const float4*>(x);
        for (int idx = tid; idx < 64 * 16; idx += 256) {
            int nn = idx >> 4, ig = idx & 15;
            float4 v = __ldg(&xg[((size_t)b * N0 + n0 + nn) * 16 + ig]);
            float* p = &xs[nn * 65 + ig * 4];
            p[0] = v.x; p[1] = v.y; p[2] = v.z; p[3] = v.w;
        }
    }
    __syncthreads();

    // reconstruct a1 window: pairs rr = 2m, 2m+1 (m = 0..17), window 35 used
    for (int idx = tid; idx < 64 * 18; idx += 256) {
        int c = idx / 18, m = idx - c * 18;
        const float* A = &sA2[c * 22 + m];
        const float* D = &sD2[c * 22 + m];
        u64 accE = 0ull, accO = 0ull;
#pragma unroll
        for (int t = 0; t < 4; t++) {
            u64 ad = pk2(A[t], D[t]);
            accE = ffma2(ad, lh[2 * t + 1], accE);
            accO = ffma2(ad, lh[2 * t], accO);
        }
        float2 e = up2(accE), o = up2(accO);
        sA[c * 36 + 2 * m] = e.x + e.y;
        sA[c * 36 + 2 * m + 1] = o.x + o.y;
    }
    __syncthreads();

    // IDWT level 1 into ys[nn][c]: pairs nn = 2m, 2m+1 (m = 0..31)
    for (int idx = tid; idx < 64 * 32; idx += 256) {
        int c = idx >> 5, m = idx & 31;
        const float* A = &sA[c * 36 + m];
        const float* D = &sD[c * 36 + m];
        u64 accE = 0ull, accO = 0ull;
#pragma unroll
        for (int t = 0; t < 4; t++) {
            u64 ad = pk2(A[t], D[t]);
            accE = ffma2(ad, lh[2 * t + 1], accE);
            accO = ffma2(ad, lh[2 * t], accO);
        }
        float2 e = up2(accE), o = up2(accO);
        ys[(2 * m) * 65 + c] = e.x + e.y;
        ys[(2 * m + 1) * 65 + c] = o.x + o.y;
    }
    __syncthreads();

    // dense shortcut (f32x2) + add + mish; thread: 2 nn (nn, nn+32) x 8 c
    int nn = tid >> 3;
    int lg = tid & 7;
    int g = lg * 4;
    const ulonglong2* dk2 = reinterpret_cast<const ulonglong2*>(dks);
    u64 bi0 = pk2(bs[g], bs[g + 1]);
    u64 bi1 = pk2(bs[g + 2], bs[g + 3]);
    u64 bi2 = pk2(bs[g + 32], bs[g + 33]);
    u64 bi3 = pk2(bs[g + 34], bs[g + 35]);
    u64 a00 = bi0, a01 = bi1, a02 = bi2, a03 = bi3;
    u64 a10 = bi0, a11 = bi1, a12 = bi2, a13 = bi3;
#pragma unroll
    for (int i = 0; i < 64; i++) {
        float xv0 = xs[nn * 65 + i];
        float xv1 = xs[(nn + 32) * 65 + i];
        u64 p0 = pk2(xv0, xv0), p1 = pk2(xv1, xv1);
        ulonglong2 w0 = dk2[i * 16 + lg];
        ulonglong2 w1 = dk2[i * 16 + 8 + lg];
        a00 = ffma2(p0, w0.x, a00); a01 = ffma2(p0, w0.y, a01);
        a02 = ffma2(p0, w1.x, a02); a03 = ffma2(p0, w1.y, a03);
        a10 = ffma2(p1, w0.x, a10); a11 = ffma2(p1, w0.y, a11);
        a12 = ffma2(p1, w1.x, a12); a13 = ffma2(p1, w1.y, a13);
    }
#pragma unroll
    for (int h = 0; h < 2; h++) {
        int row = nn + h * 32;
        float2 q0_ = up2(h ? a10 : a00), q1_ = up2(h ? a11 : a01);
        float2 q2_ = up2(h ? a12 : a02), q3_ = up2(h ? a13 : a03);
        float v0[4] = {q0_.x, q0_.y, q1_.x, q1_.y};
        float v1[4] = {q2_.x, q2_.y, q3_.x, q3_.y};
#pragma unroll
        for (int u = 0; u < 4; u++) {
            v0[u] = mish_f(v0[u] + ys[row * 65 + g + u]);
            v1[u] = mish_f(v1[u] + ys[row * 65 + g + 32 + u]);
        }
        float4* op = reinterpret_cast<float4*>(&out[((size_t)b * N0 + n0 + row) * CB]);
        op[lg] = make_float4(v0[0], v0[1], v0[2], v0[3]);
        op[8 + lg] = make_float4(v1[0], v1[1], v1[2], v1[3]);
    }
}

// ---------------------------------------------------------------------------
extern "C" void kernel_launch(void* const* d_in, const int* in_sizes, int n_in,
                              void* d_out, int out_size) {
    (void)in_sizes; (void)n_in; (void)out_size;
    const float* x    = (const float*)d_in[0];
    const float* w1   = (const float*)d_in[1];
    const float* w2   = (const float*)d_in[2];
    const float* dk   = (const float*)d_in[3];
    const float* bias = (const float*)d_in[4];
    float* out = (float*)d_out;

    float *d1, *a2, *d2, *d3, *a4, *d4;
    float *a4t, *d4t, *a4mt, *d4mt, *a4m, *d4m, *wt1, *wt2;
    cudaGetSymbolAddress((void**)&d1,   g_d1);
    cudaGetSymbolAddress((void**)&a2,   g_a2);
    cudaGetSymbolAddress((void**)&d2,   g_d2);
    cudaGetSymbolAddress((void**)&d3,   g_d3);
    cudaGetSymbolAddress((void**)&a4,   g_a4);
    cudaGetSymbolAddress((void**)&d4,   g_d4);
    cudaGetSymbolAddress((void**)&a4t,  g_a4t);
    cudaGetSymbolAddress((void**)&d4t,  g_d4t);
    cudaGetSymbolAddress((void**)&a4mt, g_a4mt);
    cudaGetSymbolAddress((void**)&d4mt, g_d4mt);
    cudaGetSymbolAddress((void**)&a4m,  g_a4m);
    cudaGetSymbolAddress((void**)&d4m,  g_d4m);
    cudaGetSymbolAddress((void**)&wt1,  g_wt1);
    cudaGetSymbolAddress((void**)&wt2,  g_wt2);

    const int K1_SMEM = (2 * 32 * 139 + 2 * 32 * 68) * (int)sizeof(float);  // 52992 B
    const int K7_SMEM = (4096 + 4160 + 4160 + 2304 + 2304 + 1408 + 1408 + 64) * (int)sizeof(float); // 79616 B
    cudaFuncSetAttribute(dwt12_kernel, cudaFuncAttributeMaxDynamicSharedMemorySize, K1_SMEM);
    cudaFuncSetAttribute(ifinal2_kernel, cudaFuncAttributeMaxDynamicSharedMemorySize, K7_SMEM);

    dim3 trb(32, 8);
    // 1. fused transpose + DWT L1 + L2
    dwt12_kernel<<<dim3(33, 64), 256, K1_SMEM>>>(x, d1, a2, d2);
    // 2. fused DWT L3 + L4
    dwt34_kernel<<<R_TOT, 256>>>(a2, d3, a4, d4);
    // 3. forward transposes
    tr4_kernel<<<dim3((M4 + 31) / 32, 4096 / 32, 4), trb>>>(a4, d4, w1, w2, a4t, d4t, wt1, wt2);
    // 4. channel mix
    mix_kernel<<<dim3(M4, 2), 256>>>(a4t, d4t, wt1, wt2, a4mt, d4mt);
    // 5. transpose mixed back
    tr2_kernel<<<dim3(R_TOT / 32, (M4 + 31) / 32, 2), trb>>>(a4mt, d4mt, a4m, d4m);
    // 6. fused IDWT L4->3->2
    idwt432_kernel<<<R_TOT, 256>>>(a4m, d4m, d3, a2);
    // 7. fused IDWT L2->1 + L1->0 + dense (f32x2) + mish, 64-wide n-tiles
    ifinal2_kernel<<<dim3(N0 / 64, BB), 256, K7_SMEM>>>(a2, d2, d1, x, dk, bias, out);
}